// round 5
// baseline (speedup 1.0000x reference)
#include <cuda_runtime.h>
#include <cstdint>

#define NODES_MAX 50048
#define EDGES_MAX 800000
#define IN_C  128
#define HID_C 128
#define OUT_C 64

// ---------------- device scratch ----------------
__device__ float  g_h   [(size_t)NODES_MAX * HID_C];
__device__ float  g_agg [(size_t)NODES_MAX * HID_C];
__device__ float  g_h2  [(size_t)NODES_MAX * OUT_C];
__device__ int    g_idx_is64;

// CSR-by-dst scratch
__device__ int    g_counts [NODES_MAX];
__device__ int    g_partial[NODES_MAX];
__device__ int    g_bsum   [64];
__device__ int    g_row_off[NODES_MAX + 1];
__device__ int    g_cursor [NODES_MAX];
__device__ float2 g_csr_sw [EDGES_MAX];   // .x = src idx (int bits), .y = weight

// ---------------- packed f32x2 helpers ----------------
__device__ __forceinline__ unsigned long long bcast2(float a) {
    unsigned long long r;
    unsigned int au = __float_as_uint(a);
    asm("mov.b64 %0, {%1, %1};" : "=l"(r) : "r"(au));
    return r;
}
#define FFMA2(acc, a2, b2) \
    asm("fma.rn.f32x2 %0, %1, %2, %0;" : "+l"(acc) : "l"(a2), "l"(b2))

// ---------------- index dtype detection ----------------
__global__ void detect_idx_kernel(const int* __restrict__ ei_words) {
    int lane = threadIdx.x & 31;
    int bad = 0;
    for (int k = lane; k < 1024; k += 32)
        if (ei_words[2 * k + 1] != 0) bad = 1;
    bad = __any_sync(0xffffffffu, bad);
    if (lane == 0) g_idx_is64 = bad ? 0 : 1;
}

__device__ __forceinline__ void load_sd(const int* __restrict__ ei, int e, int E,
                                        int is64, int& s, int& d) {
    if (is64) { s = ei[2 * e]; d = ei[2 * E + 2 * e]; }
    else      { s = ei[e];     d = ei[E + e]; }
}

__device__ __forceinline__ int load_d(const int* __restrict__ ei, int e, int E, int is64) {
    return is64 ? ei[2 * E + 2 * e] : ei[E + e];
}

// ---------------- CSR build ----------------
__global__ void zero_counts_kernel(int n) {
    int i = blockIdx.x * blockDim.x + threadIdx.x;
    if (i < n) g_counts[i] = 0;
}

__global__ void hist_kernel(const int* __restrict__ ei, int E) {
    int base = (blockIdx.x * blockDim.x + threadIdx.x) * 4;
    int is64 = g_idx_is64;
    int d0 = -1, d1 = -1, d2 = -1, d3 = -1;
    if (base + 0 < E) d0 = load_d(ei, base + 0, E, is64);
    if (base + 1 < E) d1 = load_d(ei, base + 1, E, is64);
    if (base + 2 < E) d2 = load_d(ei, base + 2, E, is64);
    if (base + 3 < E) d3 = load_d(ei, base + 3, E, is64);
    if (d0 >= 0) atomicAdd(&g_counts[d0], 1);
    if (d1 >= 0) atomicAdd(&g_counts[d1], 1);
    if (d2 >= 0) atomicAdd(&g_counts[d2], 1);
    if (d3 >= 0) atomicAdd(&g_counts[d3], 1);
}

__global__ __launch_bounds__(1024) void scan_local_kernel(int n) {
    __shared__ int sh[1024];
    int t = threadIdx.x;
    int idx = blockIdx.x * 1024 + t;
    int v = (idx < n) ? g_counts[idx] : 0;
    sh[t] = v;
    __syncthreads();
#pragma unroll
    for (int off = 1; off < 1024; off <<= 1) {
        int x = (t >= off) ? sh[t - off] : 0;
        __syncthreads();
        sh[t] += x;
        __syncthreads();
    }
    if (idx < n) g_partial[idx] = sh[t] - v;
    if (t == 1023) g_bsum[blockIdx.x] = sh[1023];
}

__global__ void scan_bsum_kernel(int nb) {
    if (threadIdx.x == 0) {
        int acc = 0;
        for (int i = 0; i < nb; i++) { int v = g_bsum[i]; g_bsum[i] = acc; acc += v; }
    }
}

__global__ __launch_bounds__(1024) void scan_add_kernel(int n, int E) {
    int idx = blockIdx.x * 1024 + threadIdx.x;
    if (idx < n) {
        g_row_off[idx] = g_partial[idx] + g_bsum[idx >> 10];
        g_cursor[idx]  = 0;
    } else if (idx == n) {
        g_row_off[n] = E;
    }
}

__global__ void fill_kernel(const int* __restrict__ ei, const float* __restrict__ ew, int E) {
    int e = blockIdx.x * blockDim.x + threadIdx.x;
    if (e >= E) return;
    int s, d;
    load_sd(ei, e, E, g_idx_is64, s, d);
    int pos = g_row_off[d] + atomicAdd(&g_cursor[d], 1);
    g_csr_sw[pos] = make_float2(__int_as_float(s), ew[e]);
}

// ---------------- GEMM1: h[M,128] = x[M,128] @ W1[128,128], f32x2 core ----------------
__global__ __launch_bounds__(128) void gemm1_kernel(
    const float* __restrict__ x, const float* __restrict__ W, int M)
{
    __shared__ float As[32][64];
    __shared__ float Bs[32][128];

    const int tid = threadIdx.x;
    const int ty  = tid >> 4;
    const int tx  = tid & 15;
    const int rowBase = blockIdx.x * 64;

    unsigned long long acc2[8][4];   // 8 rows x 4 packed col-pairs (8 cols)
#pragma unroll
    for (int i = 0; i < 8; i++)
#pragma unroll
        for (int j = 0; j < 4; j++) acc2[i][j] = 0ull;

    for (int kt = 0; kt < IN_C; kt += 32) {
#pragma unroll
        for (int i = 0; i < 4; i++) {
            int idx = tid + i * 128;
            int r   = idx >> 3;
            int kv  = idx & 7;
            int grow = rowBase + r;
            float4 v = make_float4(0.f, 0.f, 0.f, 0.f);
            if (grow < M)
                v = *reinterpret_cast<const float4*>(x + (size_t)grow * IN_C + kt + kv * 4);
            As[kv * 4 + 0][r] = v.x;
            As[kv * 4 + 1][r] = v.y;
            As[kv * 4 + 2][r] = v.z;
            As[kv * 4 + 3][r] = v.w;
        }
#pragma unroll
        for (int i = 0; i < 8; i++) {
            int idx = tid + i * 128;
            int kk  = idx >> 5;
            int nv  = idx & 31;
            *reinterpret_cast<float4*>(&Bs[kk][nv * 4]) =
                *reinterpret_cast<const float4*>(W + (size_t)(kt + kk) * HID_C + nv * 4);
        }
        __syncthreads();

#pragma unroll
        for (int k = 0; k < 32; k++) {
            float a[8];
            *reinterpret_cast<float4*>(&a[0]) = *reinterpret_cast<float4*>(&As[k][ty * 8]);
            *reinterpret_cast<float4*>(&a[4]) = *reinterpret_cast<float4*>(&As[k][ty * 8 + 4]);
            const unsigned long long* bp =
                reinterpret_cast<const unsigned long long*>(&Bs[k][tx * 8]);
            unsigned long long b0 = bp[0], b1 = bp[1], b2 = bp[2], b3 = bp[3];
#pragma unroll
            for (int i = 0; i < 8; i++) {
                unsigned long long ai = bcast2(a[i]);
                FFMA2(acc2[i][0], ai, b0);
                FFMA2(acc2[i][1], ai, b1);
                FFMA2(acc2[i][2], ai, b2);
                FFMA2(acc2[i][3], ai, b3);
            }
        }
        __syncthreads();
    }

#pragma unroll
    for (int i = 0; i < 8; i++) {
        int grow = rowBase + ty * 8 + i;
        if (grow < M) {
            unsigned long long* op =
                reinterpret_cast<unsigned long long*>(g_h + (size_t)grow * HID_C + tx * 8);
            op[0] = acc2[i][0]; op[1] = acc2[i][1];
            op[2] = acc2[i][2]; op[3] = acc2[i][3];
        }
    }
}

// ---------------- gather1: agg[i] = sum_j w_j * h[src_j], 128 ch ----------------
__global__ __launch_bounds__(256) void gather1_kernel(int n)
{
    int node = (blockIdx.x * blockDim.x + threadIdx.x) >> 5;
    int lane = threadIdx.x & 31;
    if (node >= n) return;
    int beg = g_row_off[node];
    int end = g_row_off[node + 1];

    float4 acc0 = make_float4(0.f, 0.f, 0.f, 0.f);
    float4 acc1 = make_float4(0.f, 0.f, 0.f, 0.f);
    int j = beg;
    for (; j + 1 < end; j += 2) {
        float2 p0 = g_csr_sw[j];
        float2 p1 = g_csr_sw[j + 1];
        int   s0 = __float_as_int(p0.x);
        int   s1 = __float_as_int(p1.x);
        float w0 = p0.y, w1 = p1.y;
        float4 v0 = *reinterpret_cast<const float4*>(g_h + (size_t)s0 * HID_C + lane * 4);
        float4 v1 = *reinterpret_cast<const float4*>(g_h + (size_t)s1 * HID_C + lane * 4);
        acc0.x += w0 * v0.x; acc0.y += w0 * v0.y; acc0.z += w0 * v0.z; acc0.w += w0 * v0.w;
        acc1.x += w1 * v1.x; acc1.y += w1 * v1.y; acc1.z += w1 * v1.z; acc1.w += w1 * v1.w;
    }
    if (j < end) {
        float2 p0 = g_csr_sw[j];
        int   s0 = __float_as_int(p0.x);
        float w0 = p0.y;
        float4 v0 = *reinterpret_cast<const float4*>(g_h + (size_t)s0 * HID_C + lane * 4);
        acc0.x += w0 * v0.x; acc0.y += w0 * v0.y; acc0.z += w0 * v0.z; acc0.w += w0 * v0.w;
    }
    acc0.x += acc1.x; acc0.y += acc1.y; acc0.z += acc1.z; acc0.w += acc1.w;
    *reinterpret_cast<float4*>(g_agg + (size_t)node * HID_C + lane * 4) = acc0;
}

// ---------------- GEMM2: h2[M,64] = relu(agg[M,128]+b1) @ W2[128,64], f32x2 core ----------------
__global__ __launch_bounds__(128) void gemm2_kernel(
    const float* __restrict__ W2, const float* __restrict__ b1, int M)
{
    __shared__ float As[32][128];
    __shared__ float Bs[32][64];

    const int tid = threadIdx.x;
    const int ty  = tid >> 3;
    const int tx  = tid & 7;
    const int rowBase = blockIdx.x * 128;

    unsigned long long acc2[8][4];
#pragma unroll
    for (int i = 0; i < 8; i++)
#pragma unroll
        for (int j = 0; j < 4; j++) acc2[i][j] = 0ull;

    for (int kt = 0; kt < HID_C; kt += 32) {
#pragma unroll
        for (int i = 0; i < 8; i++) {
            int idx = tid + i * 128;
            int r   = idx >> 3;
            int kv  = idx & 7;
            int grow = rowBase + r;
            float4 v = make_float4(0.f, 0.f, 0.f, 0.f);
            if (grow < M) {
                v = *reinterpret_cast<const float4*>(g_agg + (size_t)grow * HID_C + kt + kv * 4);
                float4 bv = *reinterpret_cast<const float4*>(b1 + kt + kv * 4);
                v.x = fmaxf(v.x + bv.x, 0.f);
                v.y = fmaxf(v.y + bv.y, 0.f);
                v.z = fmaxf(v.z + bv.z, 0.f);
                v.w = fmaxf(v.w + bv.w, 0.f);
            }
            As[kv * 4 + 0][r] = v.x;
            As[kv * 4 + 1][r] = v.y;
            As[kv * 4 + 2][r] = v.z;
            As[kv * 4 + 3][r] = v.w;
        }
#pragma unroll
        for (int i = 0; i < 4; i++) {
            int idx = tid + i * 128;
            int kk  = idx >> 4;
            int nv  = idx & 15;
            *reinterpret_cast<float4*>(&Bs[kk][nv * 4]) =
                *reinterpret_cast<const float4*>(W2 + (size_t)(kt + kk) * OUT_C + nv * 4);
        }
        __syncthreads();

#pragma unroll
        for (int k = 0; k < 32; k++) {
            float a[8];
            *reinterpret_cast<float4*>(&a[0]) = *reinterpret_cast<float4*>(&As[k][ty * 8]);
            *reinterpret_cast<float4*>(&a[4]) = *reinterpret_cast<float4*>(&As[k][ty * 8 + 4]);
            const unsigned long long* bp =
                reinterpret_cast<const unsigned long long*>(&Bs[k][tx * 8]);
            unsigned long long b0 = bp[0], b1v = bp[1], b2 = bp[2], b3 = bp[3];
#pragma unroll
            for (int i = 0; i < 8; i++) {
                unsigned long long ai = bcast2(a[i]);
                FFMA2(acc2[i][0], ai, b0);
                FFMA2(acc2[i][1], ai, b1v);
                FFMA2(acc2[i][2], ai, b2);
                FFMA2(acc2[i][3], ai, b3);
            }
        }
        __syncthreads();
    }

#pragma unroll
    for (int i = 0; i < 8; i++) {
        int grow = rowBase + ty * 8 + i;
        if (grow < M) {
            unsigned long long* op =
                reinterpret_cast<unsigned long long*>(g_h2 + (size_t)grow * OUT_C + tx * 8);
            op[0] = acc2[i][0]; op[1] = acc2[i][1];
            op[2] = acc2[i][2]; op[3] = acc2[i][3];
        }
    }
}

// ---------------- gather2: out[i] = b2 + sum_j h2[src_j], 64 ch ----------------
__global__ __launch_bounds__(256) void gather2_kernel(
    float* __restrict__ out, const float* __restrict__ b2, int n)
{
    int node = (blockIdx.x * blockDim.x + threadIdx.x) >> 5;
    int lane = threadIdx.x & 31;
    if (node >= n) return;
    int beg = g_row_off[node];
    int end = g_row_off[node + 1];

    float2 acc0 = make_float2(0.f, 0.f);
    float2 acc1 = make_float2(0.f, 0.f);
    int j = beg;
    for (; j + 1 < end; j += 2) {
        int s0 = __float_as_int(g_csr_sw[j].x);
        int s1 = __float_as_int(g_csr_sw[j + 1].x);
        float2 v0 = *reinterpret_cast<const float2*>(g_h2 + (size_t)s0 * OUT_C + lane * 2);
        float2 v1 = *reinterpret_cast<const float2*>(g_h2 + (size_t)s1 * OUT_C + lane * 2);
        acc0.x += v0.x; acc0.y += v0.y;
        acc1.x += v1.x; acc1.y += v1.y;
    }
    if (j < end) {
        int s0 = __float_as_int(g_csr_sw[j].x);
        float2 v0 = *reinterpret_cast<const float2*>(g_h2 + (size_t)s0 * OUT_C + lane * 2);
        acc0.x += v0.x; acc0.y += v0.y;
    }
    float2 bv = *reinterpret_cast<const float2*>(b2 + lane * 2);
    acc0.x += acc1.x + bv.x;
    acc0.y += acc1.y + bv.y;
    *reinterpret_cast<float2*>(out + (size_t)node * OUT_C + lane * 2) = acc0;
}

// ---------------- launch ----------------
extern "C" void kernel_launch(void* const* d_in, const int* in_sizes, int n_in,
                              void* d_out, int out_size)
{
    const float* x   = (const float*)d_in[0];
    const int*   ei  = (const int*)d_in[1];
    const float* ew  = (const float*)d_in[2];
    const float* W1  = (const float*)d_in[3];
    const float* b1  = (const float*)d_in[4];
    const float* W2  = (const float*)d_in[5];
    const float* b2  = (const float*)d_in[6];
    float*       out = (float*)d_out;

    const int N = in_sizes[0] / IN_C;
    const int E = in_sizes[2];
    const int nScanBlocks = (N + 1023) / 1024;

    static cudaStream_t s_side = nullptr;
    static cudaEvent_t  s_fork = nullptr, s_join = nullptr;
    if (s_side == nullptr) {
        cudaStreamCreateWithFlags(&s_side, cudaStreamNonBlocking);
        cudaEventCreateWithFlags(&s_fork, cudaEventDisableTiming);
        cudaEventCreateWithFlags(&s_join, cudaEventDisableTiming);
    }

    detect_idx_kernel<<<1, 32>>>(ei);

    cudaEventRecord(s_fork, 0);
    cudaStreamWaitEvent(s_side, s_fork, 0);

    zero_counts_kernel<<<(N + 255) / 256, 256, 0, s_side>>>(N);
    hist_kernel<<<(E / 4 + 255) / 256, 256, 0, s_side>>>(ei, E);
    scan_local_kernel<<<nScanBlocks, 1024, 0, s_side>>>(N);
    scan_bsum_kernel<<<1, 1, 0, s_side>>>(nScanBlocks);
    scan_add_kernel<<<nScanBlocks + 1, 1024, 0, s_side>>>(N, E);
    fill_kernel<<<(E + 255) / 256, 256, 0, s_side>>>(ei, ew, E);
    cudaEventRecord(s_join, s_side);

    gemm1_kernel<<<(N + 63) / 64, 128>>>(x, W1, N);

    cudaStreamWaitEvent(0, s_join, 0);

    gather1_kernel<<<(N * 32 + 255) / 256, 256>>>(N);
    gemm2_kernel<<<(N + 127) / 128, 128>>>(W2, b1, N);
    gather2_kernel<<<(N * 32 + 255) / 256, 256>>>(out, b2, N);
}

// round 6
// speedup vs baseline: 1.0409x; 1.0409x over previous
#include <cuda_runtime.h>
#include <cstdint>

#define NODES_MAX 50048
#define EDGES_MAX 800000
#define IN_C  128
#define HID_C 128
#define OUT_C 64

// ---------------- device scratch ----------------
__device__ float  g_h   [(size_t)NODES_MAX * HID_C];   // x @ W1
__device__ float  g_agg [(size_t)NODES_MAX * HID_C];   // relu(gather + b1)
__device__ float  g_h2  [(size_t)NODES_MAX * OUT_C];   // agg @ W2
__device__ int    g_idx_is64;

// CSR-by-dst scratch
__device__ int    g_counts [NODES_MAX];
__device__ int    g_partial[NODES_MAX];
__device__ int    g_bsum   [64];
__device__ int    g_row_off[NODES_MAX + 1];
__device__ int    g_cursor [NODES_MAX];
__device__ float2 g_csr_sw [EDGES_MAX];   // .x = src idx (int bits), .y = weight

// ---------------- zero counts + detect idx dtype (merged) ----------------
// int64 indices < 50000 -> every odd 32-bit word is 0.
__global__ void zero_detect_kernel(const int* __restrict__ ei_words, int n) {
    int i = blockIdx.x * blockDim.x + threadIdx.x;
    if (i < n) g_counts[i] = 0;
    if (blockIdx.x == 0 && threadIdx.x < 32) {
        int lane = threadIdx.x;
        int bad = 0;
        for (int k = lane; k < 1024; k += 32)
            if (ei_words[2 * k + 1] != 0) bad = 1;
        bad = __any_sync(0xffffffffu, bad);
        if (lane == 0) g_idx_is64 = bad ? 0 : 1;
    }
}

__device__ __forceinline__ void load_sd(const int* __restrict__ ei, int e, int E,
                                        int is64, int& s, int& d) {
    if (is64) { s = ei[2 * e]; d = ei[2 * E + 2 * e]; }
    else      { s = ei[e];     d = ei[E + e]; }
}

__device__ __forceinline__ int load_d(const int* __restrict__ ei, int e, int E, int is64) {
    return is64 ? ei[2 * E + 2 * e] : ei[E + e];
}

// ---------------- CSR build ----------------
__global__ void hist_kernel(const int* __restrict__ ei, int E) {
    int base = (blockIdx.x * blockDim.x + threadIdx.x) * 4;
    int is64 = g_idx_is64;
    int d0 = -1, d1 = -1, d2 = -1, d3 = -1;
    if (base + 0 < E) d0 = load_d(ei, base + 0, E, is64);
    if (base + 1 < E) d1 = load_d(ei, base + 1, E, is64);
    if (base + 2 < E) d2 = load_d(ei, base + 2, E, is64);
    if (base + 3 < E) d3 = load_d(ei, base + 3, E, is64);
    if (d0 >= 0) atomicAdd(&g_counts[d0], 1);
    if (d1 >= 0) atomicAdd(&g_counts[d1], 1);
    if (d2 >= 0) atomicAdd(&g_counts[d2], 1);
    if (d3 >= 0) atomicAdd(&g_counts[d3], 1);
}

__global__ __launch_bounds__(1024) void scan_local_kernel(int n) {
    __shared__ int sh[1024];
    int t = threadIdx.x;
    int idx = blockIdx.x * 1024 + t;
    int v = (idx < n) ? g_counts[idx] : 0;
    sh[t] = v;
    __syncthreads();
#pragma unroll
    for (int off = 1; off < 1024; off <<= 1) {
        int x = (t >= off) ? sh[t - off] : 0;
        __syncthreads();
        sh[t] += x;
        __syncthreads();
    }
    if (idx < n) g_partial[idx] = sh[t] - v;
    if (t == 1023) g_bsum[blockIdx.x] = sh[1023];
}

__global__ void scan_bsum_kernel(int nb) {
    if (threadIdx.x == 0) {
        int acc = 0;
        for (int i = 0; i < nb; i++) { int v = g_bsum[i]; g_bsum[i] = acc; acc += v; }
    }
}

__global__ __launch_bounds__(1024) void scan_add_kernel(int n, int E) {
    int idx = blockIdx.x * 1024 + threadIdx.x;
    if (idx < n) {
        g_row_off[idx] = g_partial[idx] + g_bsum[idx >> 10];
        g_cursor[idx]  = 0;
    } else if (idx == n) {
        g_row_off[n] = E;
    }
}

__global__ void fill_kernel(const int* __restrict__ ei, const float* __restrict__ ew, int E) {
    int e = blockIdx.x * blockDim.x + threadIdx.x;
    if (e >= E) return;
    int s, d;
    load_sd(ei, e, E, g_idx_is64, s, d);
    int pos = g_row_off[d] + atomicAdd(&g_cursor[d], 1);
    g_csr_sw[pos] = make_float2(__int_as_float(s), ew[e]);
}

// ---------------- GEMM1: h[M,128] = x[M,128] @ W1[128,128] (FFMA core) ----------------
__global__ __launch_bounds__(128) void gemm1_kernel(
    const float* __restrict__ x, const float* __restrict__ W, int M)
{
    __shared__ float As[32][64];
    __shared__ float Bs[32][128];

    const int tid = threadIdx.x;
    const int ty  = tid >> 4;
    const int tx  = tid & 15;
    const int rowBase = blockIdx.x * 64;

    float acc[8][8];
#pragma unroll
    for (int i = 0; i < 8; i++)
#pragma unroll
        for (int j = 0; j < 8; j++) acc[i][j] = 0.f;

    for (int kt = 0; kt < IN_C; kt += 32) {
#pragma unroll
        for (int i = 0; i < 4; i++) {
            int idx = tid + i * 128;
            int r   = idx >> 3;
            int kv  = idx & 7;
            int grow = rowBase + r;
            float4 v = make_float4(0.f, 0.f, 0.f, 0.f);
            if (grow < M)
                v = *reinterpret_cast<const float4*>(x + (size_t)grow * IN_C + kt + kv * 4);
            As[kv * 4 + 0][r] = v.x;
            As[kv * 4 + 1][r] = v.y;
            As[kv * 4 + 2][r] = v.z;
            As[kv * 4 + 3][r] = v.w;
        }
#pragma unroll
        for (int i = 0; i < 8; i++) {
            int idx = tid + i * 128;
            int kk  = idx >> 5;
            int nv  = idx & 31;
            *reinterpret_cast<float4*>(&Bs[kk][nv * 4]) =
                *reinterpret_cast<const float4*>(W + (size_t)(kt + kk) * HID_C + nv * 4);
        }
        __syncthreads();

#pragma unroll
        for (int k = 0; k < 32; k++) {
            float a[8], b[8];
            *reinterpret_cast<float4*>(&a[0]) = *reinterpret_cast<float4*>(&As[k][ty * 8]);
            *reinterpret_cast<float4*>(&a[4]) = *reinterpret_cast<float4*>(&As[k][ty * 8 + 4]);
            *reinterpret_cast<float4*>(&b[0]) = *reinterpret_cast<float4*>(&Bs[k][tx * 8]);
            *reinterpret_cast<float4*>(&b[4]) = *reinterpret_cast<float4*>(&Bs[k][tx * 8 + 4]);
#pragma unroll
            for (int i = 0; i < 8; i++)
#pragma unroll
                for (int j = 0; j < 8; j++) acc[i][j] += a[i] * b[j];
        }
        __syncthreads();
    }

#pragma unroll
    for (int i = 0; i < 8; i++) {
        int grow = rowBase + ty * 8 + i;
        if (grow < M) {
#pragma unroll
            for (int j = 0; j < 8; j += 4)
                *reinterpret_cast<float4*>(g_h + (size_t)grow * HID_C + tx * 8 + j) =
                    make_float4(acc[i][j], acc[i][j + 1], acc[i][j + 2], acc[i][j + 3]);
        }
    }
}

// ---------------- gather1: agg[i] = relu(b1 + sum_j w_j*h[src_j]), 128 ch ----------------
// One warp per node; lane owns a float4. 4-way edge unroll for MLP.
__global__ __launch_bounds__(256) void gather1_kernel(const float* __restrict__ b1, int n)
{
    int node = (blockIdx.x * blockDim.x + threadIdx.x) >> 5;
    int lane = threadIdx.x & 31;
    if (node >= n) return;
    int beg = g_row_off[node];
    int end = g_row_off[node + 1];

    float4 acc0 = make_float4(0.f, 0.f, 0.f, 0.f);
    float4 acc1 = make_float4(0.f, 0.f, 0.f, 0.f);
    float4 acc2 = make_float4(0.f, 0.f, 0.f, 0.f);
    float4 acc3 = make_float4(0.f, 0.f, 0.f, 0.f);
    int j = beg;
    for (; j + 3 < end; j += 4) {
        float2 p0 = g_csr_sw[j];
        float2 p1 = g_csr_sw[j + 1];
        float2 p2 = g_csr_sw[j + 2];
        float2 p3 = g_csr_sw[j + 3];
        const float4* r0 = reinterpret_cast<const float4*>(g_h + (size_t)__float_as_int(p0.x) * HID_C) + lane;
        const float4* r1 = reinterpret_cast<const float4*>(g_h + (size_t)__float_as_int(p1.x) * HID_C) + lane;
        const float4* r2 = reinterpret_cast<const float4*>(g_h + (size_t)__float_as_int(p2.x) * HID_C) + lane;
        const float4* r3 = reinterpret_cast<const float4*>(g_h + (size_t)__float_as_int(p3.x) * HID_C) + lane;
        float4 v0 = *r0, v1 = *r1, v2 = *r2, v3 = *r3;
        acc0.x += p0.y * v0.x; acc0.y += p0.y * v0.y; acc0.z += p0.y * v0.z; acc0.w += p0.y * v0.w;
        acc1.x += p1.y * v1.x; acc1.y += p1.y * v1.y; acc1.z += p1.y * v1.z; acc1.w += p1.y * v1.w;
        acc2.x += p2.y * v2.x; acc2.y += p2.y * v2.y; acc2.z += p2.y * v2.z; acc2.w += p2.y * v2.w;
        acc3.x += p3.y * v3.x; acc3.y += p3.y * v3.y; acc3.z += p3.y * v3.z; acc3.w += p3.y * v3.w;
    }
    for (; j < end; j++) {
        float2 p0 = g_csr_sw[j];
        float4 v0 = *(reinterpret_cast<const float4*>(g_h + (size_t)__float_as_int(p0.x) * HID_C) + lane);
        acc0.x += p0.y * v0.x; acc0.y += p0.y * v0.y; acc0.z += p0.y * v0.z; acc0.w += p0.y * v0.w;
    }
    acc0.x += acc1.x + acc2.x + acc3.x;
    acc0.y += acc1.y + acc2.y + acc3.y;
    acc0.z += acc1.z + acc2.z + acc3.z;
    acc0.w += acc1.w + acc2.w + acc3.w;
    // fused bias + relu (sum is complete here)
    float4 bv = *(reinterpret_cast<const float4*>(b1) + lane);
    acc0.x = fmaxf(acc0.x + bv.x, 0.f);
    acc0.y = fmaxf(acc0.y + bv.y, 0.f);
    acc0.z = fmaxf(acc0.z + bv.z, 0.f);
    acc0.w = fmaxf(acc0.w + bv.w, 0.f);
    *(reinterpret_cast<float4*>(g_agg + (size_t)node * HID_C) + lane) = acc0;
}

// ---------------- GEMM2: h2[M,64] = agg[M,128] @ W2[128,64] (agg pre-activated) ----------------
__global__ __launch_bounds__(128) void gemm2_kernel(const float* __restrict__ W2, int M)
{
    __shared__ float As[32][128];
    __shared__ float Bs[32][64];

    const int tid = threadIdx.x;
    const int ty  = tid >> 3;
    const int tx  = tid & 7;
    const int rowBase = blockIdx.x * 128;

    float acc[8][8];
#pragma unroll
    for (int i = 0; i < 8; i++)
#pragma unroll
        for (int j = 0; j < 8; j++) acc[i][j] = 0.f;

    for (int kt = 0; kt < HID_C; kt += 32) {
#pragma unroll
        for (int i = 0; i < 8; i++) {
            int idx = tid + i * 128;
            int r   = idx >> 3;
            int kv  = idx & 7;
            int grow = rowBase + r;
            float4 v = make_float4(0.f, 0.f, 0.f, 0.f);
            if (grow < M)
                v = *reinterpret_cast<const float4*>(g_agg + (size_t)grow * HID_C + kt + kv * 4);
            As[kv * 4 + 0][r] = v.x;
            As[kv * 4 + 1][r] = v.y;
            As[kv * 4 + 2][r] = v.z;
            As[kv * 4 + 3][r] = v.w;
        }
#pragma unroll
        for (int i = 0; i < 4; i++) {
            int idx = tid + i * 128;
            int kk  = idx >> 4;
            int nv  = idx & 15;
            *reinterpret_cast<float4*>(&Bs[kk][nv * 4]) =
                *reinterpret_cast<const float4*>(W2 + (size_t)(kt + kk) * OUT_C + nv * 4);
        }
        __syncthreads();

#pragma unroll
        for (int k = 0; k < 32; k++) {
            float a[8], b[8];
            *reinterpret_cast<float4*>(&a[0]) = *reinterpret_cast<float4*>(&As[k][ty * 8]);
            *reinterpret_cast<float4*>(&a[4]) = *reinterpret_cast<float4*>(&As[k][ty * 8 + 4]);
            *reinterpret_cast<float4*>(&b[0]) = *reinterpret_cast<float4*>(&Bs[k][tx * 8]);
            *reinterpret_cast<float4*>(&b[4]) = *reinterpret_cast<float4*>(&Bs[k][tx * 8 + 4]);
#pragma unroll
            for (int i = 0; i < 8; i++)
#pragma unroll
                for (int j = 0; j < 8; j++) acc[i][j] += a[i] * b[j];
        }
        __syncthreads();
    }

#pragma unroll
    for (int i = 0; i < 8; i++) {
        int grow = rowBase + ty * 8 + i;
        if (grow < M) {
#pragma unroll
            for (int j = 0; j < 8; j += 4)
                *reinterpret_cast<float4*>(g_h2 + (size_t)grow * OUT_C + tx * 8 + j) =
                    make_float4(acc[i][j], acc[i][j + 1], acc[i][j + 2], acc[i][j + 3]);
        }
    }
}

// ---------------- gather2: out[i] = b2 + sum_j h2[src_j], 64 ch, 4-way unroll ----------------
__global__ __launch_bounds__(256) void gather2_kernel(
    float* __restrict__ out, const float* __restrict__ b2, int n)
{
    int node = (blockIdx.x * blockDim.x + threadIdx.x) >> 5;
    int lane = threadIdx.x & 31;
    if (node >= n) return;
    int beg = g_row_off[node];
    int end = g_row_off[node + 1];

    float2 acc0 = make_float2(0.f, 0.f);
    float2 acc1 = make_float2(0.f, 0.f);
    float2 acc2 = make_float2(0.f, 0.f);
    float2 acc3 = make_float2(0.f, 0.f);
    int j = beg;
    for (; j + 3 < end; j += 4) {
        int s0 = __float_as_int(g_csr_sw[j].x);
        int s1 = __float_as_int(g_csr_sw[j + 1].x);
        int s2 = __float_as_int(g_csr_sw[j + 2].x);
        int s3 = __float_as_int(g_csr_sw[j + 3].x);
        float2 v0 = *(reinterpret_cast<const float2*>(g_h2 + (size_t)s0 * OUT_C) + lane);
        float2 v1 = *(reinterpret_cast<const float2*>(g_h2 + (size_t)s1 * OUT_C) + lane);
        float2 v2 = *(reinterpret_cast<const float2*>(g_h2 + (size_t)s2 * OUT_C) + lane);
        float2 v3 = *(reinterpret_cast<const float2*>(g_h2 + (size_t)s3 * OUT_C) + lane);
        acc0.x += v0.x; acc0.y += v0.y;
        acc1.x += v1.x; acc1.y += v1.y;
        acc2.x += v2.x; acc2.y += v2.y;
        acc3.x += v3.x; acc3.y += v3.y;
    }
    for (; j < end; j++) {
        int s0 = __float_as_int(g_csr_sw[j].x);
        float2 v0 = *(reinterpret_cast<const float2*>(g_h2 + (size_t)s0 * OUT_C) + lane);
        acc0.x += v0.x; acc0.y += v0.y;
    }
    float2 bv = *(reinterpret_cast<const float2*>(b2) + lane);
    acc0.x += acc1.x + acc2.x + acc3.x + bv.x;
    acc0.y += acc1.y + acc2.y + acc3.y + bv.y;
    *(reinterpret_cast<float2*>(out + (size_t)node * OUT_C) + lane) = acc0;
}

// ---------------- launch ----------------
extern "C" void kernel_launch(void* const* d_in, const int* in_sizes, int n_in,
                              void* d_out, int out_size)
{
    const float* x   = (const float*)d_in[0];
    const int*   ei  = (const int*)d_in[1];
    const float* ew  = (const float*)d_in[2];
    const float* W1  = (const float*)d_in[3];
    const float* b1  = (const float*)d_in[4];
    const float* W2  = (const float*)d_in[5];
    const float* b2  = (const float*)d_in[6];
    float*       out = (float*)d_out;

    const int N = in_sizes[0] / IN_C;
    const int E = in_sizes[2];
    const int nScanBlocks = (N + 1023) / 1024;

    static cudaStream_t s_side = nullptr;
    static cudaEvent_t  s_fork = nullptr, s_join = nullptr;
    if (s_side == nullptr) {
        cudaStreamCreateWithFlags(&s_side, cudaStreamNonBlocking);
        cudaEventCreateWithFlags(&s_fork, cudaEventDisableTiming);
        cudaEventCreateWithFlags(&s_join, cudaEventDisableTiming);
    }

    // main: zero counts + detect dtype (side branch depends on both)
    zero_detect_kernel<<<(N + 255) / 256, 256>>>(ei, N);

    // fork: CSR build on side stream, concurrent with gemm1 on main
    cudaEventRecord(s_fork, 0);
    cudaStreamWaitEvent(s_side, s_fork, 0);

    hist_kernel<<<(E / 4 + 255) / 256, 256, 0, s_side>>>(ei, E);
    scan_local_kernel<<<nScanBlocks, 1024, 0, s_side>>>(N);
    scan_bsum_kernel<<<1, 1, 0, s_side>>>(nScanBlocks);
    scan_add_kernel<<<nScanBlocks + 1, 1024, 0, s_side>>>(N, E);
    fill_kernel<<<(E + 255) / 256, 256, 0, s_side>>>(ei, ew, E);
    cudaEventRecord(s_join, s_side);

    // main: dense layer-1 GEMM (independent of CSR)
    gemm1_kernel<<<(N + 63) / 64, 128>>>(x, W1, N);

    // join: gather1 needs both gemm1 (main) and CSR (side)
    cudaStreamWaitEvent(0, s_join, 0);

    gather1_kernel<<<(N * 32 + 255) / 256, 256>>>(b1, N);
    gemm2_kernel<<<(N + 127) / 128, 128>>>(W2, N);
    gather2_kernel<<<(N * 32 + 255) / 256, 256>>>(out, b2, N);
}